// round 1
// baseline (speedup 1.0000x reference)
#include <cuda_runtime.h>
#include <math.h>

#define B_DIM 64
#define D_DIM 65536
#define NT    1024
#define EPT   (D_DIM / NT)   // 64 elements per thread
#define CAP   4096           // shared candidate-list capacity

// Global accumulators (no device-memory allocation allowed; __device__ globals are the
// sanctioned scratch). Zeroed by mbl_init each launch -> deterministic.
__device__ float g_loc_sum;
__device__ float g_conf_sum;
__device__ int   g_pos_total;
__device__ int   g_sel_total;

// softplus(x) = log(1+e^x) = max(x,0) + log1p(exp(-|x|))  (exactly the reference's bce form)
__device__ __forceinline__ float softplus_f(float x) {
    return fmaxf(x, 0.0f) + log1pf(expf(-fabsf(x)));
}
__device__ __forceinline__ float sl1f(float d) {
    float ad = fabsf(d);
    return (ad < 1.0f) ? 0.5f * d * d : (ad - 0.5f);
}
// Monotone uint key: order(key) == order(float). key==0 reserved for positives
// (reference gives positives bce_neg = 0, ranking below every real negative).
__device__ __forceinline__ unsigned int key_of(float x) {
    unsigned int u = __float_as_uint(x);
    return (u & 0x80000000u) ? ~u : (u | 0x80000000u);
}
__device__ __forceinline__ float val_of_key(unsigned int k) {
    unsigned int u = (k & 0x80000000u) ? (k & 0x7FFFFFFFu) : ~k;
    return __uint_as_float(u);
}

__global__ void mbl_init() {
    g_loc_sum = 0.0f; g_conf_sum = 0.0f; g_pos_total = 0; g_sel_total = 0;
}

// Block-cooperative descending select over a 4096-bin histogram.
// Finds bin b such that the cumulative count of bins (b, 4095] is < k and
// of [b, 4095] is >= k. Returns b and cnt_gt (count strictly above b) via shared.
__device__ __forceinline__ void hist_select_4096(
    const int* hist, int* s1, int* s2, int k, int t, int* out_bin, int* out_cg)
{
    s1[t] = hist[4*t+0] + hist[4*t+1] + hist[4*t+2] + hist[4*t+3];
    __syncthreads();
    if (t < 32) {
        int s = 0;
        #pragma unroll
        for (int j = 0; j < 32; j++) s += s1[t * 32 + j];
        s2[t] = s;
    }
    __syncthreads();
    if (t == 0) {
        int acc = 0;
        int seg = 0, tt = 0, bin = 0;
        for (int j = 31; j >= 0; j--) {
            if (acc + s2[j] >= k) { seg = j; break; }
            acc += s2[j];
        }
        tt = seg * 32;
        for (int j = 31; j >= 0; j--) {
            int idx = seg * 32 + j;
            if (acc + s1[idx] >= k) { tt = idx; break; }
            acc += s1[idx];
        }
        bin = tt * 4;
        for (int j = 3; j >= 0; j--) {
            int idx = tt * 4 + j;
            if (acc + hist[idx] >= k) { bin = idx; break; }
            acc += hist[idx];
        }
        *out_bin = bin;
        *out_cg  = acc;
    }
    __syncthreads();
}

__global__ void __launch_bounds__(NT, 1) mbl_main(
    const float* __restrict__ loc_data,
    const float* __restrict__ conf_data,
    const float* __restrict__ loc_t,
    const int*   __restrict__ conf_t)
{
    __shared__ int          hist[4096];
    __shared__ int          s1[NT];
    __shared__ int          s2[32];
    __shared__ float        fbuf[NT];
    __shared__ unsigned int list[CAP];
    __shared__ int          cnt3[256];
    __shared__ float        sum3[256];
    __shared__ int          sh_bin, sh_cg, sh_nlist;

    const int t   = threadIdx.x;
    const int row = blockIdx.x;
    const size_t base = (size_t)row * D_DIM;
    const float* cd = conf_data + base;
    const int*   ct = conf_t    + base;

    for (int j = t; j < 4096; j += NT) hist[j] = 0;
    if (t == 0) sh_nlist = 0;
    __syncthreads();

    // ---------------- Pass 1: pos stats, sparse loc loss, level-1 histogram ------------
    int   npos   = 0;
    float posbce = 0.0f;
    float locs   = 0.0f;
    #pragma unroll 4
    for (int j = 0; j < EPT; j++) {
        int i = t + j * NT;
        float x  = cd[i];
        int   tv = ct[i];
        unsigned int key = 0u;
        if (tv > 0) {
            npos   += 1;
            posbce += softplus_f(-x);  // bce(x, t=1)
            float4 a  = reinterpret_cast<const float4*>(loc_data)[base + i];
            float4 bb = reinterpret_cast<const float4*>(loc_t)[base + i];
            locs += sl1f(a.x - bb.x) + sl1f(a.y - bb.y)
                  + sl1f(a.z - bb.z) + sl1f(a.w - bb.w);
        } else {
            key = key_of(x);
        }
        atomicAdd(&hist[key >> 20], 1);
    }

    // Block reductions (npos, locs, posbce)
    s1[t] = npos; __syncthreads();
    for (int s = NT / 2; s > 0; s >>= 1) { if (t < s) s1[t] += s1[t + s]; __syncthreads(); }
    int npos_row = s1[0]; __syncthreads();

    fbuf[t] = locs; __syncthreads();
    for (int s = NT / 2; s > 0; s >>= 1) { if (t < s) fbuf[t] += fbuf[t + s]; __syncthreads(); }
    float locs_row = fbuf[0]; __syncthreads();

    fbuf[t] = posbce; __syncthreads();
    for (int s = NT / 2; s > 0; s >>= 1) { if (t < s) fbuf[t] += fbuf[t + s]; __syncthreads(); }
    float posbce_row = fbuf[0]; __syncthreads();

    int k = min(3 * npos_row, D_DIM);   // num_neg for this row
    if (t == 0) {
        atomicAdd(&g_pos_total, npos_row);
        atomicAdd(&g_loc_sum,   locs_row);
        atomicAdd(&g_sel_total, npos_row + k);
    }

    // ---------------- Level-1 select ----------------
    hist_select_4096(hist, s1, s2, k, t, &sh_bin, &sh_cg);
    int b1 = sh_bin;
    int r1 = k - sh_cg;

    for (int j = t; j < 4096; j += NT) hist[j] = 0;
    __syncthreads();

    // ---------------- Pass 2: sum above b1, level-2 histogram + candidate list --------
    float csum = 0.0f;
    #pragma unroll 2
    for (int j = 0; j < EPT; j++) {
        int i = t + j * NT;
        float x  = cd[i];
        int   tv = ct[i];
        unsigned int key = (tv > 0) ? 0u : key_of(x);
        int hb = (int)(key >> 20);
        if (hb > b1) {
            csum += softplus_f(x);           // bce(x, t=0), strictly inside top-k
        } else if (hb == b1) {
            atomicAdd(&hist[(key >> 8) & 0xFFFu], 1);
            int p = atomicAdd(&sh_nlist, 1);
            if (p < CAP) list[p] = key;
        }
    }
    __syncthreads();

    // ---------------- Level-2 select ----------------
    hist_select_4096(hist, s1, s2, r1, t, &sh_bin, &sh_cg);
    int b2 = sh_bin;
    int r2 = r1 - sh_cg;
    int nlist = sh_nlist;

    if (t < 256) { cnt3[t] = 0; sum3[t] = 0.0f; }
    __syncthreads();

    // ---------------- Pass 3: level-3 (exact, 8 low bits) ----------------
    if (nlist <= CAP) {
        // Fast path: candidates are in shared memory
        for (int p = t; p < nlist; p += NT) {
            unsigned int key = list[p];
            int mb = (int)((key >> 8) & 0xFFFu);
            float v = (key == 0u) ? 0.0f : softplus_f(val_of_key(key));
            if (mb > b2) {
                csum += v;
            } else if (mb == b2) {
                atomicAdd(&cnt3[key & 0xFFu], 1);
                atomicAdd(&sum3[key & 0xFFu], v);
            }
        }
    } else {
        // Fallback: re-scan the row (rare; only if candidate bin is huge)
        for (int j = 0; j < EPT; j++) {
            int i = t + j * NT;
            float x  = cd[i];
            int   tv = ct[i];
            unsigned int key = (tv > 0) ? 0u : key_of(x);
            if ((int)(key >> 20) == b1) {
                int mb = (int)((key >> 8) & 0xFFFu);
                float v = (key == 0u) ? 0.0f : softplus_f(x);
                if (mb > b2) {
                    csum += v;
                } else if (mb == b2) {
                    atomicAdd(&cnt3[key & 0xFFu], 1);
                    atomicAdd(&sum3[key & 0xFFu], v);
                }
            }
        }
    }
    __syncthreads();

    // Reduce the bce partial sums
    fbuf[t] = csum; __syncthreads();
    for (int s = NT / 2; s > 0; s >>= 1) { if (t < s) fbuf[t] += fbuf[t + s]; __syncthreads(); }

    if (t == 0) {
        float conf_row = fbuf[0] + posbce_row;
        // Final 256-bin descending walk: fully resolves the 32-bit threshold key.
        int acc = 0; float slo = 0.0f; int b3 = 255;
        for (int j = 255; j >= 0; j--) {
            if (acc + cnt3[j] >= r2) { b3 = j; break; }
            acc += cnt3[j];
            slo += sum3[j];
        }
        int r3 = r2 - acc;     // exact number of threshold-valued elements to include
        float bceT = 0.0f;
        if (r3 > 0) {
            unsigned int keyT = ((unsigned int)b1 << 20) | ((unsigned int)b2 << 8)
                              | (unsigned int)b3;
            bceT = (keyT == 0u) ? 0.0f : softplus_f(val_of_key(keyT));
        }
        conf_row += slo + (float)r3 * bceT;
        atomicAdd(&g_conf_sum, conf_row);
    }
}

__global__ void mbl_fin(float* out) {
    float P = (float)g_pos_total;
    float loss_l = g_loc_sum / (4.0f * P * P);                  // (sum / (4P)) / N, N==P
    float loss_c = g_conf_sum / ((float)g_sel_total * P);
    out[0] = loss_l;
    out[1] = loss_c;
}

extern "C" void kernel_launch(void* const* d_in, const int* in_sizes, int n_in,
                              void* d_out, int out_size)
{
    // Identify inputs robustly by element count:
    //   loc_data / loc_t : B*D*4 = 16777216   (in dict order: loc_data first)
    //   conf_data / conf_t: B*D  = 4194304    (conf_data first)
    const float* loc_data  = nullptr;
    const float* loc_tgt   = nullptr;
    const float* conf_data = nullptr;
    const int*   conf_tgt  = nullptr;
    for (int i = 0; i < n_in; i++) {
        if (in_sizes[i] == B_DIM * D_DIM * 4) {
            if (!loc_data) loc_data = (const float*)d_in[i];
            else           loc_tgt  = (const float*)d_in[i];
        } else {
            if (!conf_data) conf_data = (const float*)d_in[i];
            else            conf_tgt  = (const int*)d_in[i];
        }
    }

    mbl_init<<<1, 1>>>();
    mbl_main<<<B_DIM, NT>>>(loc_data, conf_data, loc_tgt, conf_tgt);
    mbl_fin<<<1, 1>>>((float*)d_out);
}